// round 8
// baseline (speedup 1.0000x reference)
#include <cuda_runtime.h>
#include <cstdint>
#include <math.h>

// GWNN on GB300 — mma.sync tf32. Big GEMMs use 64x64 warp tiles (8 MACs per
// smem byte -> crossbar demand 896 cyc/iter vs 2048 MMA cyc: tensor-bound).
// Feature-major intermediates; producer epilogues RN-round to tf32.
//   tT = w1T (x) x          K=512  splitK2 + combine(rnd)
//   uT = (tT (x) Winv)*f1   K=8192 splitK2 + combine(*f1, rnd)
//   hT = relu(uT (x) W)     K=8192 splitK2 + combine(relu, rnd)
//   sT = w2T @ hT           K=256 SIMT (rnd)
//   vT = (sT (x) Winv)*f2   K=8192 splitK4 + combine(*f2, rnd)
//   oT = vT (x) W           K=8192 splitK4 (log-softmax sums partials)

#define NR   8192
#define FIN  512
#define HID  256
#define OUTD 64

__device__ float g_w1T[HID * FIN];
__device__ float g_tT [HID * NR];
__device__ float g_uT [HID * NR];
__device__ float g_hT [HID * NR];
__device__ float g_sT [OUTD * NR];
__device__ float g_vT [OUTD * NR];
__device__ float g_bp [2 * HID * NR];     // big-GEMM split-K partials
__device__ float g_part[4 * OUTD * NR];   // layer-2 split-K partials

// ---------------- PTX helpers ----------------------------------------------
__device__ __forceinline__ uint32_t smem_u32(const void* p) {
    uint32_t a;
    asm("{ .reg .u64 t; cvta.to.shared.u64 t, %1; cvt.u32.u64 %0, t; }" : "=r"(a) : "l"(p));
    return a;
}
#define SWZ(x) ((x) ^ (((x) >> 3) & 0x70))

__device__ __forceinline__ void cp_async16(uint32_t dst, const void* src) {
    asm volatile("cp.async.cg.shared.global [%0], [%1], 16;" :: "r"(dst), "l"(src));
}
__device__ __forceinline__ void cp_commit() {
    asm volatile("cp.async.commit_group;" ::: "memory");
}
template <int N>
__device__ __forceinline__ void cp_wait() {
    asm volatile("cp.async.wait_group %0;" :: "n"(N) : "memory");
}
__device__ __forceinline__ void ldsm_x4(uint32_t& r0, uint32_t& r1, uint32_t& r2, uint32_t& r3,
                                        uint32_t addr) {
    asm volatile("ldmatrix.sync.aligned.m8n8.x4.shared.b16 {%0,%1,%2,%3}, [%4];"
                 : "=r"(r0), "=r"(r1), "=r"(r2), "=r"(r3) : "r"(addr));
}
__device__ __forceinline__ float rna_tf32(float x) {
    uint32_t y;
    asm("cvt.rna.tf32.f32 %0, %1;" : "=r"(y) : "f"(x));
    return __uint_as_float(y);
}
__device__ __forceinline__ void mma_tf32(float& d0, float& d1, float& d2, float& d3,
                                         uint32_t a0, uint32_t a1, uint32_t a2, uint32_t a3,
                                         uint32_t b0, uint32_t b1) {
    asm volatile("mma.sync.aligned.m16n8k8.row.col.f32.tf32.tf32.f32 "
                 "{%0,%1,%2,%3}, {%4,%5,%6,%7}, {%8,%9}, {%0,%1,%2,%3};"
                 : "+f"(d0), "+f"(d1), "+f"(d2), "+f"(d3)
                 : "r"(a0), "r"(a1), "r"(a2), "r"(a3), "r"(b0), "r"(b1));
}

// ---------------- mma.sync tf32 GEMM ----------------------------------------
// D[BM, BN] tile of A[M,K]*B[N,K]^T; A,B K-major (stride Kfull), C stride NR.
// Split-K via gridDim.z: each z does Kchunk; C += z * cstride.
// 256 threads, 8 warps (2 m x 4 n). Warp tile (MT*16) x (NT*8).
// BM = MT*32, BN = NT*32. S-stage multistage, one __syncthreads per K32 iter.
// Big GEMMs: MT=4, NT=8 (warp 64x64, CTA 128x256, tensor-bound).
// Layer-2:   MT=2, NT=4 (warp 32x32, CTA 64x128).
template <int MT, int NT, int S, int EPI, int RND>
__global__ __launch_bounds__(256)
void mm_mma_kernel(const float* __restrict__ A, const float* __restrict__ B,
                   float* __restrict__ C, int Kfull, int Kchunk, size_t cstride,
                   const float* __restrict__ colscale)
{
    constexpr int BM = MT * 32, BN = NT * 32;
    constexpr int NP = NT / 2;            // ldmatrix.x4 B loads per k-step
    constexpr int AI = BM / 32;           // A cp.async passes (256 thr, 32 rows)
    constexpr int BI = BN / 32;
    constexpr int A_BYTES = BM * 128;     // BK=32 floats = 128 B/row
    constexpr int B_BYTES = BN * 128;
    constexpr int STAGE   = A_BYTES + B_BYTES;

    extern __shared__ char smem[];
    const uint32_t sb = smem_u32(smem);
    const int tid    = threadIdx.x;
    const int wid    = tid >> 5;
    const int lane   = tid & 31;
    const int warp_m = wid & 1;
    const int warp_n = wid >> 1;

    const int m0 = blockIdx.y * BM;
    const int n0 = blockIdx.x * BN;
    const int k0 = blockIdx.z * Kchunk;
    C += (size_t)blockIdx.z * cstride;

    const float* Ab = A + (size_t)m0 * Kfull + k0;
    const float* Bb = B + (size_t)n0 * Kfull + k0;
    const int KT = Kchunk >> 5;

    // ---- loader addressing: 32 rows/pass (tid>>3), col = (tid&7)*16B ----
    const int lr = tid >> 3;              // 0..31
    const int lc = tid & 7;               // 0..7
    const float* aP0 = Ab + (size_t)lr * Kfull + lc * 4;
    const float* bP0 = Bb + (size_t)lr * Kfull + lc * 4;
    const size_t rstep = (size_t)32 * Kfull;
    const uint32_t d0 = SWZ(lr * 128 + lc * 16);    // +4096/pass swizzle-invariant

    // ---- ldmatrix addressing ----
    const int a_row  = warp_m * (MT * 16) + (lane & 15);
    const int a_byte = (lane >> 4) << 4;
    const int b_row  = warp_n * (NT * 8) + ((lane >> 4) << 3) + (lane & 7);
    const int b_byte = (lane & 8) << 1;

    float acc[MT][NT][4];
    #pragma unroll
    for (int mt = 0; mt < MT; ++mt)
        #pragma unroll
        for (int nt = 0; nt < NT; ++nt)
            #pragma unroll
            for (int q = 0; q < 4; ++q) acc[mt][nt][q] = 0.0f;

    auto load_stage = [&](int stg) {
        const uint32_t as = sb + (stg % S) * STAGE;
        const uint32_t bs = as + A_BYTES;
        const int koff = stg << 5;
        #pragma unroll
        for (int it = 0; it < AI; ++it)
            cp_async16(as + d0 + it * 4096, aP0 + it * rstep + koff);
        #pragma unroll
        for (int it = 0; it < BI; ++it)
            cp_async16(bs + d0 + it * 4096, bP0 + it * rstep + koff);
    };

    #pragma unroll
    for (int p = 0; p < S - 1; ++p) {
        if (p < KT) load_stage(p);
        cp_commit();
    }

    for (int i = 0; i < KT; ++i) {
        cp_wait<S - 2>();
        __syncthreads();
        if (i + S - 1 < KT) load_stage(i + S - 1);
        cp_commit();

        const uint32_t as = sb + (i % S) * STAGE;
        const uint32_t bs = as + A_BYTES;

        #pragma unroll
        for (int ks = 0; ks < 4; ++ks) {
            uint32_t af[MT][4], bf[NP][4];
            #pragma unroll
            for (int mt = 0; mt < MT; ++mt)
                ldsm_x4(af[mt][0], af[mt][1], af[mt][2], af[mt][3],
                        as + SWZ((a_row + mt * 16) * 128 + ks * 32 + a_byte));
            #pragma unroll
            for (int np = 0; np < NP; ++np)
                ldsm_x4(bf[np][0], bf[np][1], bf[np][2], bf[np][3],
                        bs + SWZ((b_row + np * 16) * 128 + ks * 32 + b_byte));
            #pragma unroll
            for (int mt = 0; mt < MT; ++mt)
                #pragma unroll
                for (int nt = 0; nt < NT; ++nt)
                    mma_tf32(acc[mt][nt][0], acc[mt][nt][1], acc[mt][nt][2], acc[mt][nt][3],
                             af[mt][0], af[mt][1], af[mt][2], af[mt][3],
                             bf[nt >> 1][(nt & 1) * 2], bf[nt >> 1][(nt & 1) * 2 + 1]);
        }
    }

    // epilogue
    const int er = m0 + warp_m * (MT * 16) + (lane >> 2);
    const int ec = n0 + warp_n * (NT * 8) + (lane & 3) * 2;
    #pragma unroll
    for (int mt = 0; mt < MT; ++mt) {
        #pragma unroll
        for (int nt = 0; nt < NT; ++nt) {
            const int row = er + mt * 16;
            const int col = ec + nt * 8;
            float v0 = acc[mt][nt][0], v1 = acc[mt][nt][1];
            float v2 = acc[mt][nt][2], v3 = acc[mt][nt][3];
            if (EPI == 1) {
                float2 sc = *(const float2*)&colscale[col];
                v0 *= sc.x; v1 *= sc.y; v2 *= sc.x; v3 *= sc.y;
            }
            if (EPI == 2) {
                v0 = fmaxf(v0, 0.0f); v1 = fmaxf(v1, 0.0f);
                v2 = fmaxf(v2, 0.0f); v3 = fmaxf(v3, 0.0f);
            }
            if (RND) {
                v0 = rna_tf32(v0); v1 = rna_tf32(v1);
                v2 = rna_tf32(v2); v3 = rna_tf32(v3);
            }
            *(float2*)&C[(size_t)row * NR + col]       = make_float2(v0, v1);
            *(float2*)&C[(size_t)(row + 8) * NR + col] = make_float2(v2, v3);
        }
    }
}

// ---------------- small kernels ---------------------------------------------
__global__ __launch_bounds__(256)
void transpose_rna_kernel(const float* __restrict__ in, float* __restrict__ out,
                          int R, int C)
{
    __shared__ float tile[32][33];
    const int c0 = blockIdx.x * 32;
    const int r0 = blockIdx.y * 32;
    const int tx = threadIdx.x, ty = threadIdx.y;   // 32 x 8
    #pragma unroll
    for (int i = 0; i < 32; i += 8)
        tile[ty + i][tx] = in[(size_t)(r0 + ty + i) * C + c0 + tx];
    __syncthreads();
    #pragma unroll
    for (int i = 0; i < 32; i += 8)
        out[(size_t)(c0 + ty + i) * R + r0 + tx] = rna_tf32(tile[tx][ty + i]);
}

// big split-K combine: MODE 0 rna((P0+P1)*f[col]); 1 rna(relu(P0+P1)); 2 rna(P0+P1)
template <int MODE>
__global__ __launch_bounds__(256)
void combine_big_kernel(const float* __restrict__ P, const float* __restrict__ f,
                        float* __restrict__ out)
{
    constexpr size_t CH = (size_t)HID * NR;
    const size_t idx = (size_t)blockIdx.x * 256 + threadIdx.x;
    float v = P[idx] + P[idx + CH];
    if (MODE == 0) v *= f[(int)(idx & (NR - 1))];
    if (MODE == 1) v = fmaxf(v, 0.0f);
    out[idx] = rna_tf32(v);
}

// sT[j,n] = rna( sum_f w2[f,j] * hT[f,n] )   (64 x 8192, K=256) — SIMT
__global__ __launch_bounds__(256)
void gemm_small_kernel(const float* __restrict__ w2, const float* __restrict__ hT,
                       float* __restrict__ sT)
{
    __shared__ float As[32][64];
    __shared__ float Bs[32][136];
    const int tid = threadIdx.x;
    const int n0 = blockIdx.x * 128;
    const int tj = (tid >> 4) * 4;
    const int tn = (tid & 15) * 8;

    float acc[4][8];
    #pragma unroll
    for (int i = 0; i < 4; ++i)
        #pragma unroll
        for (int j = 0; j < 8; ++j) acc[i][j] = 0.0f;

    for (int f0 = 0; f0 < HID; f0 += 32) {
        #pragma unroll
        for (int it = 0; it < 8; ++it) {
            int idx = tid + it * 256;
            As[idx >> 6][idx & 63] = w2[(size_t)(f0 + (idx >> 6)) * OUTD + (idx & 63)];
        }
        #pragma unroll
        for (int it = 0; it < 4; ++it) {
            int idx = tid + it * 256;
            int f = idx >> 5, n = (idx & 31) * 4;
            *(float4*)&Bs[f][n] = *(const float4*)(hT + (size_t)(f0 + f) * NR + n0 + n);
        }
        __syncthreads();
        #pragma unroll
        for (int kk = 0; kk < 32; ++kk) {
            float a[4], b[8];
            #pragma unroll
            for (int i = 0; i < 4; ++i) a[i] = As[kk][tj + i];
            #pragma unroll
            for (int j = 0; j < 8; ++j) b[j] = Bs[kk][tn + j];
            #pragma unroll
            for (int i = 0; i < 4; ++i)
                #pragma unroll
                for (int j = 0; j < 8; ++j) acc[i][j] = fmaf(a[i], b[j], acc[i][j]);
        }
        __syncthreads();
    }
    #pragma unroll
    for (int i = 0; i < 4; ++i) {
        float* row = sT + (size_t)(tj + i) * NR + n0 + tn;
        #pragma unroll
        for (int j = 0; j < 8; ++j) row[j] = rna_tf32(acc[i][j]);
    }
}

// vT = rna( (sum_z part_z) * f2[col] )
__global__ __launch_bounds__(256)
void combine_vT_kernel(const float* __restrict__ P, const float* __restrict__ f2,
                       float* __restrict__ vT)
{
    constexpr size_t CH = (size_t)OUTD * NR;
    const size_t idx = (size_t)blockIdx.x * 256 + threadIdx.x;
    const int n = (int)(idx & (NR - 1));
    float v = P[idx] + P[idx + CH] + P[idx + 2 * CH] + P[idx + 3 * CH];
    vT[idx] = rna_tf32(v * f2[n]);
}

// out[m, j] = (sum_z P_z[j, m]) - logsumexp_j
__global__ __launch_bounds__(256)
void logsoftmax_part_kernel(const float* __restrict__ P, float* __restrict__ out)
{
    constexpr size_t CH = (size_t)OUTD * NR;
    const int m = blockIdx.x * blockDim.x + threadIdx.x;
    if (m >= NR) return;
    float v[OUTD];
    float mx = -1e30f;
    #pragma unroll
    for (int j = 0; j < OUTD; ++j) {
        const size_t base = (size_t)j * NR + m;
        v[j] = P[base] + P[base + CH] + P[base + 2 * CH] + P[base + 3 * CH];
        mx = fmaxf(mx, v[j]);
    }
    float s = 0.0f;
    #pragma unroll
    for (int j = 0; j < OUTD; ++j) s += expf(v[j] - mx);
    const float lse = mx + logf(s);
    #pragma unroll
    for (int j = 0; j < OUTD; ++j) out[(size_t)m * OUTD + j] = v[j] - lse;
}

// ---------------- kernel_launch ---------------------------------------------
extern "C" void kernel_launch(void* const* d_in, const int* in_sizes, int n_in,
                              void* d_out, int out_size)
{
    (void)in_sizes; (void)n_in; (void)out_size;
    const float* x    = (const float*)d_in[0];
    const float* W    = (const float*)d_in[1];
    const float* Winv = (const float*)d_in[2];
    const float* w1   = (const float*)d_in[3];
    const float* f1   = (const float*)d_in[4];
    const float* w2   = (const float*)d_in[5];
    const float* f2   = (const float*)d_in[6];
    float* out = (float*)d_out;

    float *w1T, *tT, *uT, *hT, *sT, *vT, *bp, *part;
    cudaGetSymbolAddress((void**)&w1T,  g_w1T);
    cudaGetSymbolAddress((void**)&tT,   g_tT);
    cudaGetSymbolAddress((void**)&uT,   g_uT);
    cudaGetSymbolAddress((void**)&hT,   g_hT);
    cudaGetSymbolAddress((void**)&sT,   g_sT);
    cudaGetSymbolAddress((void**)&vT,   g_vT);
    cudaGetSymbolAddress((void**)&bp,   g_bp);
    cudaGetSymbolAddress((void**)&part, g_part);

    // Big: MT=4 NT=8 (CTA 128x256, warp 64x64), S=3 -> 144KB, 1 CTA/SM.
    // Layer-2: MT=2 NT=4 (CTA 64x128, warp 32x32), S=4 -> 96KB, 2 CTAs/SM.
    constexpr int SMEM_BIG = 3 * (128 + 256) * 128;   // 147456
    constexpr int SMEM_SK  = 4 * (64 + 128) * 128;    // 98304
    cudaFuncSetAttribute(mm_mma_kernel<4, 8, 3, 0, 0>, cudaFuncAttributeMaxDynamicSharedMemorySize, SMEM_BIG);
    cudaFuncSetAttribute(mm_mma_kernel<2, 4, 4, 0, 0>, cudaFuncAttributeMaxDynamicSharedMemorySize, SMEM_SK);

    constexpr size_t BIG_CH = (size_t)HID * NR;
    constexpr size_t SK_CH  = (size_t)OUTD * NR;

    transpose_rna_kernel<<<dim3(HID / 32, FIN / 32), dim3(32, 8)>>>(w1, w1T, FIN, HID);

    // tT partials: w1T (x) x    [256, 8192], K=512, splitK2, grid 32x2x2
    mm_mma_kernel<4, 8, 3, 0, 0><<<dim3(NR / 256, HID / 128, 2), 256, SMEM_BIG>>>(
        w1T, x, bp, FIN, FIN / 2, BIG_CH, nullptr);
    combine_big_kernel<2><<<(int)(BIG_CH / 256), 256>>>(bp, nullptr, tT);
    // uT partials: tT (x) Winv  [256, 8192], K=8192, splitK2, grid 32x2x2
    mm_mma_kernel<4, 8, 3, 0, 0><<<dim3(NR / 256, HID / 128, 2), 256, SMEM_BIG>>>(
        tT, Winv, bp, NR, NR / 2, BIG_CH, nullptr);
    combine_big_kernel<0><<<(int)(BIG_CH / 256), 256>>>(bp, f1, uT);
    // hT partials: uT (x) W     [256, 8192], K=8192, splitK2
    mm_mma_kernel<4, 8, 3, 0, 0><<<dim3(NR / 256, HID / 128, 2), 256, SMEM_BIG>>>(
        uT, W, bp, NR, NR / 2, BIG_CH, nullptr);
    combine_big_kernel<1><<<(int)(BIG_CH / 256), 256>>>(bp, nullptr, hT);
    // sT = w2T @ hT             [64, 8192], K=256 (SIMT)
    gemm_small_kernel<<<NR / 128, 256>>>(w2, hT, sT);
    // vT partials: sT (x) Winv  [64, 8192], K=8192, splitK4, grid 64x1x4
    mm_mma_kernel<2, 4, 4, 0, 0><<<dim3(NR / 128, 1, 4), 256, SMEM_SK>>>(
        sT, Winv, part, NR, NR / 4, SK_CH, nullptr);
    combine_vT_kernel<<<(int)(SK_CH / 256), 256>>>(part, f2, vT);
    // oT partials: vT (x) W     [64, 8192], K=8192, splitK4
    mm_mma_kernel<2, 4, 4, 0, 0><<<dim3(NR / 128, 1, 4), 256, SMEM_SK>>>(
        vT, W, part, NR, NR / 4, SK_CH, nullptr);
    // out = log_softmax(sum of partials, axis=features)
    logsoftmax_part_kernel<<<NR / 256, 256>>>(part, out);
}

// round 9
// speedup vs baseline: 1.3020x; 1.3020x over previous
#include <cuda_runtime.h>
#include <cuda_fp16.h>
#include <cstdint>
#include <math.h>

// GWNN on GB300 — mma.sync fp16 (m16n8k16). fp16 mantissa == tf32 mantissa
// (eps 2^-11), values O(1) -> same accuracy, 2x tensor throughput, half the
// smem traffic. W/Winv/x converted once to fp16; intermediates stored fp16.
//   tT = w1T (x) xh         K=512  splitK2 + combine(h)
//   uT = (tT (x) Winvh)*f1  K=8192 splitK2 + combine(*f1, h)
//   hT = relu(uT (x) Wh)    K=8192 splitK2 + combine(relu, h)
//   sT = w2T @ hT           K=256 SIMT (h)
//   vT = (sT (x) Winvh)*f2  K=8192 splitK4 + combine(*f2, h)
//   oT = vT (x) Wh          K=8192 splitK4 (log-softmax sums float partials)

#define NR   8192
#define FIN  512
#define HID  256
#define OUTD 64

__device__ __half g_Wh   [(size_t)NR * NR];   // 134 MB
__device__ __half g_Winvh[(size_t)NR * NR];   // 134 MB
__device__ __half g_xh  [NR * FIN];
__device__ __half g_w1Th[HID * FIN];
__device__ __half g_tT [HID * NR];
__device__ __half g_uT [HID * NR];
__device__ __half g_hT [HID * NR];
__device__ __half g_sT [OUTD * NR];
__device__ __half g_vT [OUTD * NR];
__device__ float  g_bp [2 * HID * NR];     // big-GEMM split-K float partials
__device__ float  g_part[4 * OUTD * NR];   // layer-2 split-K float partials

// ---------------- PTX helpers ----------------------------------------------
__device__ __forceinline__ uint32_t smem_u32(const void* p) {
    uint32_t a;
    asm("{ .reg .u64 t; cvta.to.shared.u64 t, %1; cvt.u32.u64 %0, t; }" : "=r"(a) : "l"(p));
    return a;
}
#define SWZ(x) ((x) ^ (((x) >> 3) & 0x70))

__device__ __forceinline__ void cp_async16(uint32_t dst, const void* src) {
    asm volatile("cp.async.cg.shared.global [%0], [%1], 16;" :: "r"(dst), "l"(src));
}
__device__ __forceinline__ void cp_commit() {
    asm volatile("cp.async.commit_group;" ::: "memory");
}
template <int N>
__device__ __forceinline__ void cp_wait() {
    asm volatile("cp.async.wait_group %0;" :: "n"(N) : "memory");
}
__device__ __forceinline__ void ldsm_x4(uint32_t& r0, uint32_t& r1, uint32_t& r2, uint32_t& r3,
                                        uint32_t addr) {
    asm volatile("ldmatrix.sync.aligned.m8n8.x4.shared.b16 {%0,%1,%2,%3}, [%4];"
                 : "=r"(r0), "=r"(r1), "=r"(r2), "=r"(r3) : "r"(addr));
}
// mma m16n8k16 fp16 in, fp32 acc
__device__ __forceinline__ void mma_f16(float& d0, float& d1, float& d2, float& d3,
                                        uint32_t a0, uint32_t a1, uint32_t a2, uint32_t a3,
                                        uint32_t b0, uint32_t b1) {
    asm volatile("mma.sync.aligned.m16n8k16.row.col.f32.f16.f16.f32 "
                 "{%0,%1,%2,%3}, {%4,%5,%6,%7}, {%8,%9}, {%0,%1,%2,%3};"
                 : "+f"(d0), "+f"(d1), "+f"(d2), "+f"(d3)
                 : "r"(a0), "r"(a1), "r"(a2), "r"(a3), "r"(b0), "r"(b1));
}

// ---------------- fp16 mma GEMM ---------------------------------------------
// D[BM, BN] float partials of A[M,K]*B[N,K]^T; A,B fp16 K-major (stride Kfull
// halves), C float stride NR. Split-K via gridDim.z: Kchunk each, C += z*cstride.
// 256 threads, 8 warps (2 m x 4 n). Warp tile (MT*16) x (NT*8). BK=64 halves
// (128 B rows, SW128). 4 k16-steps per stage. One __syncthreads per stage.
template <int MT, int NT, int S>
__global__ __launch_bounds__(256, 2)
void mm_f16_kernel(const __half* __restrict__ A, const __half* __restrict__ B,
                   float* __restrict__ C, int Kfull, int Kchunk, size_t cstride)
{
    constexpr int BM = MT * 32, BN = NT * 32;
    constexpr int NP = NT / 2;            // B ldsm.x4 per k-step
    constexpr int AI = BM / 32;           // cp.async passes (256 thr, 32 rows)
    constexpr int BI = BN / 32;
    constexpr int A_BYTES = BM * 128;     // 64 halves = 128 B per row
    constexpr int B_BYTES = BN * 128;
    constexpr int STAGE   = A_BYTES + B_BYTES;

    extern __shared__ char smem[];
    const uint32_t sb = smem_u32(smem);
    const int tid    = threadIdx.x;
    const int wid    = tid >> 5;
    const int lane   = tid & 31;
    const int warp_m = wid & 1;
    const int warp_n = wid >> 1;

    const int m0 = blockIdx.y * BM;
    const int n0 = blockIdx.x * BN;
    const int k0 = blockIdx.z * Kchunk;
    C += (size_t)blockIdx.z * cstride;

    const __half* Ab = A + (size_t)m0 * Kfull + k0;
    const __half* Bb = B + (size_t)n0 * Kfull + k0;
    const int KT = Kchunk >> 6;           // 64 k per stage

    // loader: 32 rows/pass, 8 halves (16 B) per thread
    const int lr = tid >> 3;              // 0..31
    const int lc = tid & 7;               // 0..7
    const __half* aP0 = Ab + (size_t)lr * Kfull + lc * 8;
    const __half* bP0 = Bb + (size_t)lr * Kfull + lc * 8;
    const size_t rstep = (size_t)32 * Kfull;
    const uint32_t d0 = SWZ(lr * 128 + lc * 16);

    // ldmatrix addressing (fragment wiring identical to tf32 path)
    const int a_row  = warp_m * (MT * 16) + (lane & 15);
    const int a_byte = (lane >> 4) << 4;
    const int b_row  = warp_n * (NT * 8) + ((lane >> 4) << 3) + (lane & 7);
    const int b_byte = (lane & 8) << 1;

    float acc[MT][NT][4];
    #pragma unroll
    for (int mt = 0; mt < MT; ++mt)
        #pragma unroll
        for (int nt = 0; nt < NT; ++nt)
            #pragma unroll
            for (int q = 0; q < 4; ++q) acc[mt][nt][q] = 0.0f;

    auto load_stage = [&](int stg) {
        const uint32_t as = sb + (stg % S) * STAGE;
        const uint32_t bs = as + A_BYTES;
        const int koff = stg << 6;        // 64 halves per stage
        #pragma unroll
        for (int it = 0; it < AI; ++it)
            cp_async16(as + d0 + it * 4096, aP0 + it * rstep + koff);
        #pragma unroll
        for (int it = 0; it < BI; ++it)
            cp_async16(bs + d0 + it * 4096, bP0 + it * rstep + koff);
    };

    #pragma unroll
    for (int p = 0; p < S - 1; ++p) {
        if (p < KT) load_stage(p);
        cp_commit();
    }

    for (int i = 0; i < KT; ++i) {
        cp_wait<S - 2>();
        __syncthreads();
        if (i + S - 1 < KT) load_stage(i + S - 1);
        cp_commit();

        const uint32_t as = sb + (i % S) * STAGE;
        const uint32_t bs = as + A_BYTES;

        #pragma unroll
        for (int ks = 0; ks < 4; ++ks) {          // 4 x k16 per stage
            uint32_t af[MT][4], bf[NP][4];
            #pragma unroll
            for (int mt = 0; mt < MT; ++mt)
                ldsm_x4(af[mt][0], af[mt][1], af[mt][2], af[mt][3],
                        as + SWZ((a_row + mt * 16) * 128 + ks * 32 + a_byte));
            #pragma unroll
            for (int np = 0; np < NP; ++np)
                ldsm_x4(bf[np][0], bf[np][1], bf[np][2], bf[np][3],
                        bs + SWZ((b_row + np * 16) * 128 + ks * 32 + b_byte));
            #pragma unroll
            for (int mt = 0; mt < MT; ++mt)
                #pragma unroll
                for (int nt = 0; nt < NT; ++nt)
                    mma_f16(acc[mt][nt][0], acc[mt][nt][1], acc[mt][nt][2], acc[mt][nt][3],
                            af[mt][0], af[mt][1], af[mt][2], af[mt][3],
                            bf[nt >> 1][(nt & 1) * 2], bf[nt >> 1][(nt & 1) * 2 + 1]);
        }
    }

    // epilogue: float partials
    const int er = m0 + warp_m * (MT * 16) + (lane >> 2);
    const int ec = n0 + warp_n * (NT * 8) + (lane & 3) * 2;
    #pragma unroll
    for (int mt = 0; mt < MT; ++mt) {
        #pragma unroll
        for (int nt = 0; nt < NT; ++nt) {
            const int row = er + mt * 16;
            const int col = ec + nt * 8;
            *(float2*)&C[(size_t)row * NR + col] =
                make_float2(acc[mt][nt][0], acc[mt][nt][1]);
            *(float2*)&C[(size_t)(row + 8) * NR + col] =
                make_float2(acc[mt][nt][2], acc[mt][nt][3]);
        }
    }
}

// ---------------- small kernels ---------------------------------------------
// fp32 -> fp16 streaming convert (n multiple of 8)
__global__ __launch_bounds__(256)
void cvt_f16_kernel(const float* __restrict__ in, __half* __restrict__ out, size_t n)
{
    const size_t i = ((size_t)blockIdx.x * 256 + threadIdx.x) * 8;
    if (i >= n) return;
    float4 a = *(const float4*)(in + i);
    float4 b = *(const float4*)(in + i + 4);
    __half2 h0 = __floats2half2_rn(a.x, a.y);
    __half2 h1 = __floats2half2_rn(a.z, a.w);
    __half2 h2 = __floats2half2_rn(b.x, b.y);
    __half2 h3 = __floats2half2_rn(b.z, b.w);
    uint4 o;
    o.x = *(uint32_t*)&h0; o.y = *(uint32_t*)&h1;
    o.z = *(uint32_t*)&h2; o.w = *(uint32_t*)&h3;
    *(uint4*)(out + i) = o;
}

// out[c, r] = half(in[r, c]),  in fp32 [R, C]
__global__ __launch_bounds__(256)
void transpose_h_kernel(const float* __restrict__ in, __half* __restrict__ out,
                        int R, int C)
{
    __shared__ float tile[32][33];
    const int c0 = blockIdx.x * 32;
    const int r0 = blockIdx.y * 32;
    const int tx = threadIdx.x, ty = threadIdx.y;   // 32 x 8
    #pragma unroll
    for (int i = 0; i < 32; i += 8)
        tile[ty + i][tx] = in[(size_t)(r0 + ty + i) * C + c0 + tx];
    __syncthreads();
    #pragma unroll
    for (int i = 0; i < 32; i += 8)
        out[(size_t)(c0 + ty + i) * R + r0 + tx] = __float2half_rn(tile[tx][ty + i]);
}

// big split-K combine -> half: MODE 0 (P0+P1)*f[col]; 1 relu(P0+P1); 2 P0+P1
template <int MODE>
__global__ __launch_bounds__(256)
void combine_big_kernel(const float* __restrict__ P, const float* __restrict__ f,
                        __half* __restrict__ out)
{
    constexpr size_t CH = (size_t)HID * NR;
    const size_t idx = (size_t)blockIdx.x * 256 + threadIdx.x;
    float v = P[idx] + P[idx + CH];
    if (MODE == 0) v *= f[(int)(idx & (NR - 1))];
    if (MODE == 1) v = fmaxf(v, 0.0f);
    out[idx] = __float2half_rn(v);
}

// sT[j,n] = half( sum_f w2[f,j] * hT[f,n] )   (64 x 8192, K=256) — SIMT
__global__ __launch_bounds__(256)
void gemm_small_kernel(const float* __restrict__ w2, const __half* __restrict__ hT,
                       __half* __restrict__ sT)
{
    __shared__ float As[32][64];
    __shared__ float Bs[32][136];
    const int tid = threadIdx.x;
    const int n0 = blockIdx.x * 128;
    const int tj = (tid >> 4) * 4;
    const int tn = (tid & 15) * 8;

    float acc[4][8];
    #pragma unroll
    for (int i = 0; i < 4; ++i)
        #pragma unroll
        for (int j = 0; j < 8; ++j) acc[i][j] = 0.0f;

    for (int f0 = 0; f0 < HID; f0 += 32) {
        #pragma unroll
        for (int it = 0; it < 8; ++it) {
            int idx = tid + it * 256;
            As[idx >> 6][idx & 63] = w2[(size_t)(f0 + (idx >> 6)) * OUTD + (idx & 63)];
        }
        #pragma unroll
        for (int it = 0; it < 2; ++it) {          // 32x128 halves, 8 per thread
            int idx = tid + it * 256;
            int f = idx >> 4, n = (idx & 15) * 8;
            uint4 raw = *(const uint4*)(hT + (size_t)(f0 + f) * NR + n0 + n);
            const __half2* hp = (const __half2*)&raw;
            #pragma unroll
            for (int q = 0; q < 4; ++q) {
                float2 fv = __half22float2(hp[q]);
                Bs[f][n + q * 2]     = fv.x;
                Bs[f][n + q * 2 + 1] = fv.y;
            }
        }
        __syncthreads();
        #pragma unroll
        for (int kk = 0; kk < 32; ++kk) {
            float a[4], b[8];
            #pragma unroll
            for (int i = 0; i < 4; ++i) a[i] = As[kk][tj + i];
            #pragma unroll
            for (int j = 0; j < 8; ++j) b[j] = Bs[kk][tn + j];
            #pragma unroll
            for (int i = 0; i < 4; ++i)
                #pragma unroll
                for (int j = 0; j < 8; ++j) acc[i][j] = fmaf(a[i], b[j], acc[i][j]);
        }
        __syncthreads();
    }
    #pragma unroll
    for (int i = 0; i < 4; ++i) {
        __half* row = sT + (size_t)(tj + i) * NR + n0 + tn;
        #pragma unroll
        for (int j = 0; j < 8; ++j) row[j] = __float2half_rn(acc[i][j]);
    }
}

// vT = half( (sum_z part_z) * f2[col] )
__global__ __launch_bounds__(256)
void combine_vT_kernel(const float* __restrict__ P, const float* __restrict__ f2,
                       __half* __restrict__ vT)
{
    constexpr size_t CH = (size_t)OUTD * NR;
    const size_t idx = (size_t)blockIdx.x * 256 + threadIdx.x;
    const int n = (int)(idx & (NR - 1));
    float v = P[idx] + P[idx + CH] + P[idx + 2 * CH] + P[idx + 3 * CH];
    vT[idx] = __float2half_rn(v * f2[n]);
}

// out[m, j] = (sum_z P_z[j, m]) - logsumexp_j
__global__ __launch_bounds__(256)
void logsoftmax_part_kernel(const float* __restrict__ P, float* __restrict__ out)
{
    constexpr size_t CH = (size_t)OUTD * NR;
    const int m = blockIdx.x * blockDim.x + threadIdx.x;
    if (m >= NR) return;
    float v[OUTD];
    float mx = -1e30f;
    #pragma unroll
    for (int j = 0; j < OUTD; ++j) {
        const size_t base = (size_t)j * NR + m;
        v[j] = P[base] + P[base + CH] + P[base + 2 * CH] + P[base + 3 * CH];
        mx = fmaxf(mx, v[j]);
    }
    float s = 0.0f;
    #pragma unroll
    for (int j = 0; j < OUTD; ++j) s += expf(v[j] - mx);
    const float lse = mx + logf(s);
    #pragma unroll
    for (int j = 0; j < OUTD; ++j) out[(size_t)m * OUTD + j] = v[j] - lse;
}

// ---------------- kernel_launch ---------------------------------------------
extern "C" void kernel_launch(void* const* d_in, const int* in_sizes, int n_in,
                              void* d_out, int out_size)
{
    (void)in_sizes; (void)n_in; (void)out_size;
    const float* x    = (const float*)d_in[0];
    const float* W    = (const float*)d_in[1];
    const float* Winv = (const float*)d_in[2];
    const float* w1   = (const float*)d_in[3];
    const float* f1   = (const float*)d_in[4];
    const float* w2   = (const float*)d_in[5];
    const float* f2   = (const float*)d_in[6];
    float* out = (float*)d_out;

    __half *Wh, *Winvh, *xh, *w1Th, *tT, *uT, *hT, *sT, *vT;
    float *bp, *part;
    cudaGetSymbolAddress((void**)&Wh,    g_Wh);
    cudaGetSymbolAddress((void**)&Winvh, g_Winvh);
    cudaGetSymbolAddress((void**)&xh,    g_xh);
    cudaGetSymbolAddress((void**)&w1Th,  g_w1Th);
    cudaGetSymbolAddress((void**)&tT,    g_tT);
    cudaGetSymbolAddress((void**)&uT,    g_uT);
    cudaGetSymbolAddress((void**)&hT,    g_hT);
    cudaGetSymbolAddress((void**)&sT,    g_sT);
    cudaGetSymbolAddress((void**)&vT,    g_vT);
    cudaGetSymbolAddress((void**)&bp,    g_bp);
    cudaGetSymbolAddress((void**)&part,  g_part);

    // Big: MT=4 NT=4 (CTA 128x128), stage 32KB, S=3 -> 96KB, 2 CTAs/SM.
    // Layer-2: MT=2 NT=4 (CTA 64x128), stage 24KB, S=4 -> 96KB, 2 CTAs/SM.
    constexpr int SMEM_BIG = 3 * (128 + 128) * 128;   // 98304
    constexpr int SMEM_SK  = 4 * (64 + 128) * 128;    // 98304
    cudaFuncSetAttribute(mm_f16_kernel<4, 4, 3>, cudaFuncAttributeMaxDynamicSharedMemorySize, SMEM_BIG);
    cudaFuncSetAttribute(mm_f16_kernel<2, 4, 4>, cudaFuncAttributeMaxDynamicSharedMemorySize, SMEM_SK);

    constexpr size_t BIG_CH = (size_t)HID * NR;
    constexpr size_t SK_CH  = (size_t)OUTD * NR;
    constexpr size_t NN = (size_t)NR * NR;

    // one-time fp16 conversions
    cvt_f16_kernel<<<(int)(NN / (256 * 8)), 256>>>(W,    Wh,    NN);
    cvt_f16_kernel<<<(int)(NN / (256 * 8)), 256>>>(Winv, Winvh, NN);
    cvt_f16_kernel<<<(NR * FIN) / (256 * 8), 256>>>(x, xh, (size_t)NR * FIN);
    transpose_h_kernel<<<dim3(HID / 32, FIN / 32), dim3(32, 8)>>>(w1, w1Th, FIN, HID);

    // tT partials: w1Th (x) xh  [256, 8192], K=512, splitK2, grid 64x2x2
    mm_f16_kernel<4, 4, 3><<<dim3(NR / 128, HID / 128, 2), 256, SMEM_BIG>>>(
        w1Th, xh, bp, FIN, FIN / 2, BIG_CH);
    combine_big_kernel<2><<<(int)(BIG_CH / 256), 256>>>(bp, nullptr, tT);
    // uT partials: tT (x) Winvh [256, 8192], K=8192, splitK2
    mm_f16_kernel<4, 4, 3><<<dim3(NR / 128, HID / 128, 2), 256, SMEM_BIG>>>(
        tT, Winvh, bp, NR, NR / 2, BIG_CH);
    combine_big_kernel<0><<<(int)(BIG_CH / 256), 256>>>(bp, f1, uT);
    // hT partials: uT (x) Wh    [256, 8192], K=8192, splitK2
    mm_f16_kernel<4, 4, 3><<<dim3(NR / 128, HID / 128, 2), 256, SMEM_BIG>>>(
        uT, Wh, bp, NR, NR / 2, BIG_CH);
    combine_big_kernel<1><<<(int)(BIG_CH / 256), 256>>>(bp, nullptr, hT);
    // sT = w2T @ hT             [64, 8192], K=256 (SIMT)
    gemm_small_kernel<<<NR / 128, 256>>>(w2, hT, sT);
    // vT partials: sT (x) Winvh [64, 8192], K=8192, splitK4, grid 64x1x4
    mm_f16_kernel<2, 4, 4><<<dim3(NR / 128, 1, 4), 256, SMEM_SK>>>(
        sT, Winvh, part, NR, NR / 4, SK_CH);
    combine_vT_kernel<<<(int)(SK_CH / 256), 256>>>(part, f2, vT);
    // oT partials: vT (x) Wh    [64, 8192], K=8192, splitK4
    mm_f16_kernel<2, 4, 4><<<dim3(NR / 128, 1, 4), 256, SMEM_SK>>>(
        vT, Wh, part, NR, NR / 4, SK_CH);
    // out = log_softmax(sum of partials, axis=features)
    logsoftmax_part_kernel<<<NR / 256, 256>>>(part, out);
}

// round 10
// speedup vs baseline: 1.3210x; 1.0146x over previous
#include <cuda_runtime.h>
#include <cuda_fp16.h>
#include <cstdint>
#include <math.h>

// GWNN on GB300 — mma.sync fp16 (m16n8k16), with W/Winv fp16 conversions
// forked onto side streams (hidden under the tT/uT GEMMs in the graph).
//   tT = w1T (x) xh         K=512  direct half epilogue (no splitK)
//   uT = (tT (x) Winvh)*f1  K=8192 splitK2 + combine(*f1, h)
//   hT = relu(uT (x) Wh)    K=8192 splitK2 + combine(relu, h)
//   sT = w2T @ hT           K=256 SIMT (h)
//   vT = (sT (x) Winvh)*f2  K=8192 splitK4 + combine(*f2, h)
//   oT = vT (x) Wh          K=8192 splitK4 (log-softmax sums float partials)

#define NR   8192
#define FIN  512
#define HID  256
#define OUTD 64

__device__ __half g_Wh   [(size_t)NR * NR];   // 134 MB
__device__ __half g_Winvh[(size_t)NR * NR];   // 134 MB
__device__ __half g_xh  [NR * FIN];
__device__ __half g_w1Th[HID * FIN];
__device__ __half g_tT [HID * NR];
__device__ __half g_uT [HID * NR];
__device__ __half g_hT [HID * NR];
__device__ __half g_sT [OUTD * NR];
__device__ __half g_vT [OUTD * NR];
__device__ float  g_bp [2 * HID * NR];     // big-GEMM split-K float partials
__device__ float  g_part[4 * OUTD * NR];   // layer-2 split-K float partials

// ---------------- PTX helpers ----------------------------------------------
__device__ __forceinline__ uint32_t smem_u32(const void* p) {
    uint32_t a;
    asm("{ .reg .u64 t; cvta.to.shared.u64 t, %1; cvt.u32.u64 %0, t; }" : "=r"(a) : "l"(p));
    return a;
}
#define SWZ(x) ((x) ^ (((x) >> 3) & 0x70))

__device__ __forceinline__ void cp_async16(uint32_t dst, const void* src) {
    asm volatile("cp.async.cg.shared.global [%0], [%1], 16;" :: "r"(dst), "l"(src));
}
__device__ __forceinline__ void cp_commit() {
    asm volatile("cp.async.commit_group;" ::: "memory");
}
template <int N>
__device__ __forceinline__ void cp_wait() {
    asm volatile("cp.async.wait_group %0;" :: "n"(N) : "memory");
}
__device__ __forceinline__ void ldsm_x4(uint32_t& r0, uint32_t& r1, uint32_t& r2, uint32_t& r3,
                                        uint32_t addr) {
    asm volatile("ldmatrix.sync.aligned.m8n8.x4.shared.b16 {%0,%1,%2,%3}, [%4];"
                 : "=r"(r0), "=r"(r1), "=r"(r2), "=r"(r3) : "r"(addr));
}
// mma m16n8k16 fp16 in, fp32 acc
__device__ __forceinline__ void mma_f16(float& d0, float& d1, float& d2, float& d3,
                                        uint32_t a0, uint32_t a1, uint32_t a2, uint32_t a3,
                                        uint32_t b0, uint32_t b1) {
    asm volatile("mma.sync.aligned.m16n8k16.row.col.f32.f16.f16.f32 "
                 "{%0,%1,%2,%3}, {%4,%5,%6,%7}, {%8,%9}, {%0,%1,%2,%3};"
                 : "+f"(d0), "+f"(d1), "+f"(d2), "+f"(d3)
                 : "r"(a0), "r"(a1), "r"(a2), "r"(a3), "r"(b0), "r"(b1));
}

// ---------------- fp16 mma GEMM ---------------------------------------------
// D[BM, BN] of A[M,K]*B[N,K]^T; A,B fp16 K-major (stride Kfull halves).
// OUTH=0: float partials, C += blockIdx.z * cstride (split-K).
// OUTH=1: __half output direct (no split-K).
// 256 threads, 8 warps (2 m x 4 n). Warp tile (MT*16) x (NT*8). BK=64 halves
// (128 B rows, SW128). 4 k16-steps per stage. One __syncthreads per stage.
template <int MT, int NT, int S, int OUTH>
__global__ __launch_bounds__(256, 2)
void mm_f16_kernel(const __half* __restrict__ A, const __half* __restrict__ B,
                   void* __restrict__ Cv, int Kfull, int Kchunk, size_t cstride)
{
    constexpr int BM = MT * 32, BN = NT * 32;
    constexpr int NP = NT / 2;
    constexpr int AI = BM / 32;
    constexpr int BI = BN / 32;
    constexpr int A_BYTES = BM * 128;
    constexpr int B_BYTES = BN * 128;
    constexpr int STAGE   = A_BYTES + B_BYTES;

    extern __shared__ char smem[];
    const uint32_t sb = smem_u32(smem);
    const int tid    = threadIdx.x;
    const int wid    = tid >> 5;
    const int lane   = tid & 31;
    const int warp_m = wid & 1;
    const int warp_n = wid >> 1;

    const int m0 = blockIdx.y * BM;
    const int n0 = blockIdx.x * BN;
    const int k0 = blockIdx.z * Kchunk;

    const __half* Ab = A + (size_t)m0 * Kfull + k0;
    const __half* Bb = B + (size_t)n0 * Kfull + k0;
    const int KT = Kchunk >> 6;

    const int lr = tid >> 3;
    const int lc = tid & 7;
    const __half* aP0 = Ab + (size_t)lr * Kfull + lc * 8;
    const __half* bP0 = Bb + (size_t)lr * Kfull + lc * 8;
    const size_t rstep = (size_t)32 * Kfull;
    const uint32_t d0 = SWZ(lr * 128 + lc * 16);

    const int a_row  = warp_m * (MT * 16) + (lane & 15);
    const int a_byte = (lane >> 4) << 4;
    const int b_row  = warp_n * (NT * 8) + ((lane >> 4) << 3) + (lane & 7);
    const int b_byte = (lane & 8) << 1;

    float acc[MT][NT][4];
    #pragma unroll
    for (int mt = 0; mt < MT; ++mt)
        #pragma unroll
        for (int nt = 0; nt < NT; ++nt)
            #pragma unroll
            for (int q = 0; q < 4; ++q) acc[mt][nt][q] = 0.0f;

    auto load_stage = [&](int stg) {
        const uint32_t as = sb + (stg % S) * STAGE;
        const uint32_t bs = as + A_BYTES;
        const int koff = stg << 6;
        #pragma unroll
        for (int it = 0; it < AI; ++it)
            cp_async16(as + d0 + it * 4096, aP0 + it * rstep + koff);
        #pragma unroll
        for (int it = 0; it < BI; ++it)
            cp_async16(bs + d0 + it * 4096, bP0 + it * rstep + koff);
    };

    #pragma unroll
    for (int p = 0; p < S - 1; ++p) {
        if (p < KT) load_stage(p);
        cp_commit();
    }

    for (int i = 0; i < KT; ++i) {
        cp_wait<S - 2>();
        __syncthreads();
        if (i + S - 1 < KT) load_stage(i + S - 1);
        cp_commit();

        const uint32_t as = sb + (i % S) * STAGE;
        const uint32_t bs = as + A_BYTES;

        #pragma unroll
        for (int ks = 0; ks < 4; ++ks) {
            uint32_t af[MT][4], bf[NP][4];
            #pragma unroll
            for (int mt = 0; mt < MT; ++mt)
                ldsm_x4(af[mt][0], af[mt][1], af[mt][2], af[mt][3],
                        as + SWZ((a_row + mt * 16) * 128 + ks * 32 + a_byte));
            #pragma unroll
            for (int np = 0; np < NP; ++np)
                ldsm_x4(bf[np][0], bf[np][1], bf[np][2], bf[np][3],
                        bs + SWZ((b_row + np * 16) * 128 + ks * 32 + b_byte));
            #pragma unroll
            for (int mt = 0; mt < MT; ++mt)
                #pragma unroll
                for (int nt = 0; nt < NT; ++nt)
                    mma_f16(acc[mt][nt][0], acc[mt][nt][1], acc[mt][nt][2], acc[mt][nt][3],
                            af[mt][0], af[mt][1], af[mt][2], af[mt][3],
                            bf[nt >> 1][(nt & 1) * 2], bf[nt >> 1][(nt & 1) * 2 + 1]);
        }
    }

    const int er = m0 + warp_m * (MT * 16) + (lane >> 2);
    const int ec = n0 + warp_n * (NT * 8) + (lane & 3) * 2;
    if (OUTH) {
        __half* C = (__half*)Cv;
        #pragma unroll
        for (int mt = 0; mt < MT; ++mt)
            #pragma unroll
            for (int nt = 0; nt < NT; ++nt) {
                const int row = er + mt * 16;
                const int col = ec + nt * 8;
                *(__half2*)&C[(size_t)row * NR + col] =
                    __floats2half2_rn(acc[mt][nt][0], acc[mt][nt][1]);
                *(__half2*)&C[(size_t)(row + 8) * NR + col] =
                    __floats2half2_rn(acc[mt][nt][2], acc[mt][nt][3]);
            }
    } else {
        float* C = (float*)Cv + (size_t)blockIdx.z * cstride;
        #pragma unroll
        for (int mt = 0; mt < MT; ++mt)
            #pragma unroll
            for (int nt = 0; nt < NT; ++nt) {
                const int row = er + mt * 16;
                const int col = ec + nt * 8;
                *(float2*)&C[(size_t)row * NR + col] =
                    make_float2(acc[mt][nt][0], acc[mt][nt][1]);
                *(float2*)&C[(size_t)(row + 8) * NR + col] =
                    make_float2(acc[mt][nt][2], acc[mt][nt][3]);
            }
    }
}

// ---------------- small kernels ---------------------------------------------
__global__ __launch_bounds__(256)
void cvt_f16_kernel(const float* __restrict__ in, __half* __restrict__ out, size_t n)
{
    const size_t i = ((size_t)blockIdx.x * 256 + threadIdx.x) * 8;
    if (i >= n) return;
    float4 a = *(const float4*)(in + i);
    float4 b = *(const float4*)(in + i + 4);
    __half2 h0 = __floats2half2_rn(a.x, a.y);
    __half2 h1 = __floats2half2_rn(a.z, a.w);
    __half2 h2 = __floats2half2_rn(b.x, b.y);
    __half2 h3 = __floats2half2_rn(b.z, b.w);
    uint4 o;
    o.x = *(uint32_t*)&h0; o.y = *(uint32_t*)&h1;
    o.z = *(uint32_t*)&h2; o.w = *(uint32_t*)&h3;
    *(uint4*)(out + i) = o;
}

__global__ __launch_bounds__(256)
void transpose_h_kernel(const float* __restrict__ in, __half* __restrict__ out,
                        int R, int C)
{
    __shared__ float tile[32][33];
    const int c0 = blockIdx.x * 32;
    const int r0 = blockIdx.y * 32;
    const int tx = threadIdx.x, ty = threadIdx.y;
    #pragma unroll
    for (int i = 0; i < 32; i += 8)
        tile[ty + i][tx] = in[(size_t)(r0 + ty + i) * C + c0 + tx];
    __syncthreads();
    #pragma unroll
    for (int i = 0; i < 32; i += 8)
        out[(size_t)(c0 + ty + i) * R + r0 + tx] = __float2half_rn(tile[tx][ty + i]);
}

// big split-K combine -> half: MODE 0 (P0+P1)*f[col]; 1 relu(P0+P1)
template <int MODE>
__global__ __launch_bounds__(256)
void combine_big_kernel(const float* __restrict__ P, const float* __restrict__ f,
                        __half* __restrict__ out)
{
    constexpr size_t CH = (size_t)HID * NR;
    const size_t idx = (size_t)blockIdx.x * 256 + threadIdx.x;
    float v = P[idx] + P[idx + CH];
    if (MODE == 0) v *= f[(int)(idx & (NR - 1))];
    if (MODE == 1) v = fmaxf(v, 0.0f);
    out[idx] = __float2half_rn(v);
}

// sT[j,n] = half( sum_f w2[f,j] * hT[f,n] )   (64 x 8192, K=256) — SIMT
__global__ __launch_bounds__(256)
void gemm_small_kernel(const float* __restrict__ w2, const __half* __restrict__ hT,
                       __half* __restrict__ sT)
{
    __shared__ float As[32][64];
    __shared__ float Bs[32][136];
    const int tid = threadIdx.x;
    const int n0 = blockIdx.x * 128;
    const int tj = (tid >> 4) * 4;
    const int tn = (tid & 15) * 8;

    float acc[4][8];
    #pragma unroll
    for (int i = 0; i < 4; ++i)
        #pragma unroll
        for (int j = 0; j < 8; ++j) acc[i][j] = 0.0f;

    for (int f0 = 0; f0 < HID; f0 += 32) {
        #pragma unroll
        for (int it = 0; it < 8; ++it) {
            int idx = tid + it * 256;
            As[idx >> 6][idx & 63] = w2[(size_t)(f0 + (idx >> 6)) * OUTD + (idx & 63)];
        }
        #pragma unroll
        for (int it = 0; it < 2; ++it) {
            int idx = tid + it * 256;
            int f = idx >> 4, n = (idx & 15) * 8;
            uint4 raw = *(const uint4*)(hT + (size_t)(f0 + f) * NR + n0 + n);
            const __half2* hp = (const __half2*)&raw;
            #pragma unroll
            for (int q = 0; q < 4; ++q) {
                float2 fv = __half22float2(hp[q]);
                Bs[f][n + q * 2]     = fv.x;
                Bs[f][n + q * 2 + 1] = fv.y;
            }
        }
        __syncthreads();
        #pragma unroll
        for (int kk = 0; kk < 32; ++kk) {
            float a[4], b[8];
            #pragma unroll
            for (int i = 0; i < 4; ++i) a[i] = As[kk][tj + i];
            #pragma unroll
            for (int j = 0; j < 8; ++j) b[j] = Bs[kk][tn + j];
            #pragma unroll
            for (int i = 0; i < 4; ++i)
                #pragma unroll
                for (int j = 0; j < 8; ++j) acc[i][j] = fmaf(a[i], b[j], acc[i][j]);
        }
        __syncthreads();
    }
    #pragma unroll
    for (int i = 0; i < 4; ++i) {
        __half* row = sT + (size_t)(tj + i) * NR + n0 + tn;
        #pragma unroll
        for (int j = 0; j < 8; ++j) row[j] = __float2half_rn(acc[i][j]);
    }
}

// vT = half( (sum_z part_z) * f2[col] )
__global__ __launch_bounds__(256)
void combine_vT_kernel(const float* __restrict__ P, const float* __restrict__ f2,
                       __half* __restrict__ vT)
{
    constexpr size_t CH = (size_t)OUTD * NR;
    const size_t idx = (size_t)blockIdx.x * 256 + threadIdx.x;
    const int n = (int)(idx & (NR - 1));
    float v = P[idx] + P[idx + CH] + P[idx + 2 * CH] + P[idx + 3 * CH];
    vT[idx] = __float2half_rn(v * f2[n]);
}

// out[m, j] = (sum_z P_z[j, m]) - logsumexp_j
__global__ __launch_bounds__(256)
void logsoftmax_part_kernel(const float* __restrict__ P, float* __restrict__ out)
{
    constexpr size_t CH = (size_t)OUTD * NR;
    const int m = blockIdx.x * blockDim.x + threadIdx.x;
    if (m >= NR) return;
    float v[OUTD];
    float mx = -1e30f;
    #pragma unroll
    for (int j = 0; j < OUTD; ++j) {
        const size_t base = (size_t)j * NR + m;
        v[j] = P[base] + P[base + CH] + P[base + 2 * CH] + P[base + 3 * CH];
        mx = fmaxf(mx, v[j]);
    }
    float s = 0.0f;
    #pragma unroll
    for (int j = 0; j < OUTD; ++j) s += expf(v[j] - mx);
    const float lse = mx + logf(s);
    #pragma unroll
    for (int j = 0; j < OUTD; ++j) out[(size_t)m * OUTD + j] = v[j] - lse;
}

// ---------------- kernel_launch ---------------------------------------------
extern "C" void kernel_launch(void* const* d_in, const int* in_sizes, int n_in,
                              void* d_out, int out_size)
{
    (void)in_sizes; (void)n_in; (void)out_size;
    const float* x    = (const float*)d_in[0];
    const float* W    = (const float*)d_in[1];
    const float* Winv = (const float*)d_in[2];
    const float* w1   = (const float*)d_in[3];
    const float* f1   = (const float*)d_in[4];
    const float* w2   = (const float*)d_in[5];
    const float* f2   = (const float*)d_in[6];
    float* out = (float*)d_out;

    __half *Wh, *Winvh, *xh, *w1Th, *tT, *uT, *hT, *sT, *vT;
    float *bp, *part;
    cudaGetSymbolAddress((void**)&Wh,    g_Wh);
    cudaGetSymbolAddress((void**)&Winvh, g_Winvh);
    cudaGetSymbolAddress((void**)&xh,    g_xh);
    cudaGetSymbolAddress((void**)&w1Th,  g_w1Th);
    cudaGetSymbolAddress((void**)&tT,    g_tT);
    cudaGetSymbolAddress((void**)&uT,    g_uT);
    cudaGetSymbolAddress((void**)&hT,    g_hT);
    cudaGetSymbolAddress((void**)&sT,    g_sT);
    cudaGetSymbolAddress((void**)&vT,    g_vT);
    cudaGetSymbolAddress((void**)&bp,    g_bp);
    cudaGetSymbolAddress((void**)&part,  g_part);

    // side streams + events, created once on the (uncaptured) correctness call
    static cudaStream_t s1 = nullptr, s2 = nullptr;
    static cudaEvent_t  eFork = nullptr, e1 = nullptr, e2 = nullptr;
    if (s1 == nullptr) {
        cudaStreamCreateWithFlags(&s1, cudaStreamNonBlocking);
        cudaStreamCreateWithFlags(&s2, cudaStreamNonBlocking);
        cudaEventCreateWithFlags(&eFork, cudaEventDisableTiming);
        cudaEventCreateWithFlags(&e1, cudaEventDisableTiming);
        cudaEventCreateWithFlags(&e2, cudaEventDisableTiming);
    }

    constexpr int SMEM_BIG = 3 * (128 + 128) * 128;   // 98304
    constexpr int SMEM_SK  = 4 * (64 + 128) * 128;    // 98304
    cudaFuncSetAttribute(mm_f16_kernel<4, 4, 3, 0>, cudaFuncAttributeMaxDynamicSharedMemorySize, SMEM_BIG);
    cudaFuncSetAttribute(mm_f16_kernel<4, 4, 3, 1>, cudaFuncAttributeMaxDynamicSharedMemorySize, SMEM_BIG);
    cudaFuncSetAttribute(mm_f16_kernel<2, 4, 4, 0>, cudaFuncAttributeMaxDynamicSharedMemorySize, SMEM_SK);

    constexpr size_t BIG_CH = (size_t)HID * NR;
    constexpr size_t SK_CH  = (size_t)OUTD * NR;
    constexpr size_t NN = (size_t)NR * NR;

    // fork: big conversions on side streams (hidden under tT-prep + uT GEMM)
    cudaEventRecord(eFork, 0);
    cudaStreamWaitEvent(s1, eFork, 0);
    cvt_f16_kernel<<<(int)(NN / (256 * 8)), 256, 0, s1>>>(Winv, Winvh, NN);
    cudaEventRecord(e1, s1);
    cudaStreamWaitEvent(s2, eFork, 0);
    cvt_f16_kernel<<<(int)(NN / (256 * 8)), 256, 0, s2>>>(W, Wh, NN);
    cudaEventRecord(e2, s2);

    // main stream: small preps + tT GEMM (independent of W/Winv)
    cvt_f16_kernel<<<(NR * FIN) / (256 * 8), 256>>>(x, xh, (size_t)NR * FIN);
    transpose_h_kernel<<<dim3(HID / 32, FIN / 32), dim3(32, 8)>>>(w1, w1Th, FIN, HID);
    // tT = w1Th (x) xh  [256, 8192], K=512, direct half output, grid 64x2
    mm_f16_kernel<4, 4, 3, 1><<<dim3(NR / 128, HID / 128, 1), 256, SMEM_BIG>>>(
        w1Th, xh, tT, FIN, FIN, 0);

    // join Winvh, then uT
    cudaStreamWaitEvent(0, e1, 0);
    mm_f16_kernel<4, 4, 3, 0><<<dim3(NR / 128, HID / 128, 2), 256, SMEM_BIG>>>(
        tT, Winvh, bp, NR, NR / 2, BIG_CH);
    combine_big_kernel<0><<<(int)(BIG_CH / 256), 256>>>(bp, f1, uT);

    // join Wh, then hT
    cudaStreamWaitEvent(0, e2, 0);
    mm_f16_kernel<4, 4, 3, 0><<<dim3(NR / 128, HID / 128, 2), 256, SMEM_BIG>>>(
        uT, Wh, bp, NR, NR / 2, BIG_CH);
    combine_big_kernel<1><<<(int)(BIG_CH / 256), 256>>>(bp, nullptr, hT);

    // layer 2
    gemm_small_kernel<<<NR / 128, 256>>>(w2, hT, sT);
    mm_f16_kernel<2, 4, 4, 0><<<dim3(NR / 128, 1, 4), 256, SMEM_SK>>>(
        sT, Winvh, part, NR, NR / 4, SK_CH);
    combine_vT_kernel<<<(int)(SK_CH / 256), 256>>>(part, f2, vT);
    mm_f16_kernel<2, 4, 4, 0><<<dim3(NR / 128, 1, 4), 256, SMEM_SK>>>(
        vT, Wh, part, NR, NR / 4, SK_CH);
    logsoftmax_part_kernel<<<NR / 256, 256>>>(part, out);
}